// round 11
// baseline (speedup 1.0000x reference)
#include <cuda_runtime.h>
#include <cstdint>

typedef unsigned long long ull;

#define NN_MAX 100000
#define LDIM 64
#define HD 32
#define EDIM 4
#define NCOL 36   // 32 (W1) + 4 (W_direct) fused columns
#define NPAD 40   // NCOL padded to 5 n8-tiles

// dynamic smem layout (float offsets)
#define W_OFF_WD  0       // Wdiff f32 [64][40], cols 36-39 zero
#define W_OFF_W2  2560    // [32][32]
#define W_OFF_W3  3584    // [32][4]
#define W_OFF_B2  3712
#define W_OFF_BO  3744    // b3 only (bd folded into g_u)
#define FLAG_OFF  3748
#define TILE_OFF  3752    // *4 = 15008 B, 16B aligned
#define M_ST      68      // m-tile stride (17 f4, odd -> conflict-free)
#define C_ST      44      // c-tile stride (11 f4, odd -> conflict-free)
#define EPW       32      // edges per warp
#define PER_WARP  2176    // max(32*68, 32*44) floats, aliased
#define NWARPS    4
#define SMEM_FLOATS (TILE_OFF + NWARPS * PER_WARP)   // 12456
#define SMEM_BYTES  (SMEM_FLOATS * 4)                // 49824 -> 4 blocks/SM

// Scratch: u[node][j] = sum_k x[node][k]*[W1|Wd][k][j] + 0.5*(b1|bd)[j]
__device__ __align__(16) float g_u[NN_MAX * NCOL];

__device__ __forceinline__ ull pack2(float a) {
    ull r; asm("mov.b64 %0, {%1, %1};" : "=l"(r) : "f"(a)); return r;
}
__device__ __forceinline__ ull fma2(ull a, ull b, ull c) {
    ull d; asm("fma.rn.f32x2 %0, %1, %2, %3;" : "=l"(d) : "l"(a), "l"(b), "l"(c)); return d;
}
__device__ __forceinline__ void unpack2(ull v, float& lo, float& hi) {
    asm("mov.b64 {%0, %1}, %2;" : "=f"(lo), "=f"(hi) : "l"(v));
}
__device__ __forceinline__ unsigned tf32_of(float v) {
    unsigned r; asm("cvt.rna.tf32.f32 %0, %1;" : "=r"(r) : "f"(v)); return r;
}
__device__ __forceinline__ void split_tf32(float v, unsigned& hi, unsigned& lo) {
    hi = tf32_of(v);
    lo = tf32_of(v - __uint_as_float(hi));
}
__device__ __forceinline__ void mma_tf32(float* d, const unsigned* a,
                                         unsigned b0, unsigned b1) {
    asm("mma.sync.aligned.m16n8k8.row.col.f32.tf32.tf32.f32 "
        "{%0,%1,%2,%3}, {%4,%5,%6,%7}, {%8,%9}, {%0,%1,%2,%3};"
        : "+f"(d[0]), "+f"(d[1]), "+f"(d[2]), "+f"(d[3])
        : "r"(a[0]), "r"(a[1]), "r"(a[2]), "r"(a[3]), "r"(b0), "r"(b1));
}

// ---------------------------------------------------------------------------
// Kernel 1: per-node u = x @ [W1[:64] | Wd[:64]] + 0.5*[b1 | bd]
// (each edge adds u_s + u_t, so half-bias per node reconstitutes the bias)
// ---------------------------------------------------------------------------
__global__ void __launch_bounds__(256) precompute_u(
    const float* __restrict__ x,
    const float* __restrict__ W1,
    const float* __restrict__ Wd,
    const float* __restrict__ b1,
    const float* __restrict__ bd,
    int n_nodes)
{
    __shared__ __align__(16) float sW[LDIM][NCOL];
    __shared__ float sb[NCOL];
    int tid = threadIdx.x;
    for (int i = tid; i < LDIM * NCOL; i += 256) {
        int k = i / NCOL, j = i - k * NCOL;
        sW[k][j] = (j < HD) ? W1[k * HD + j] : Wd[k * EDIM + (j - HD)];
    }
    if (tid < NCOL) sb[tid] = 0.5f * ((tid < HD) ? b1[tid] : bd[tid - HD]);
    __syncthreads();

    int node = blockIdx.x * 256 + tid;
    if (node >= n_nodes) return;

    float acc[NCOL];
    #pragma unroll
    for (int j = 0; j < NCOL; j++) acc[j] = sb[j];

    const float4* xr = (const float4*)(x + (size_t)node * LDIM);
    #pragma unroll 4
    for (int k4 = 0; k4 < LDIM / 4; k4++) {
        float4 v = __ldg(xr + k4);
        #pragma unroll
        for (int j = 0; j < NCOL; j++) {
            acc[j] = fmaf(v.x, sW[4 * k4 + 0][j], acc[j]);
            acc[j] = fmaf(v.y, sW[4 * k4 + 1][j], acc[j]);
            acc[j] = fmaf(v.z, sW[4 * k4 + 2][j], acc[j]);
            acc[j] = fmaf(v.w, sW[4 * k4 + 3][j], acc[j]);
        }
    }
    float4* ur = (float4*)(g_u + (size_t)node * NCOL);
    #pragma unroll
    for (int j4 = 0; j4 < NCOL / 4; j4++) {
        float4 r;
        r.x = acc[4 * j4 + 0]; r.y = acc[4 * j4 + 1];
        r.z = acc[4 * j4 + 2]; r.w = acc[4 * j4 + 3];
        ur[j4] = r;
    }
}

// ---------------------------------------------------------------------------
// Kernel 2: GEMM1 on tensor cores (tf32 3-term split), scalar f32x2 tail.
// Per warp: 32 edges. m-tile [32][68] staged in smem; MMA m16n8k8 over
// M=32 (2 tiles) x N=40 (5 tiles) x K=64 (8 tiles); C-frags staged to
// c-tile [32][44]; u added RMW; per-thread tail (GEMM2 residual + GEMM3).
// ---------------------------------------------------------------------------
__global__ void __launch_bounds__(128, 4) edge_kernel(
    const float* __restrict__ x,
    const void* __restrict__ ei,
    const float* __restrict__ W1, const float* __restrict__ b1,
    const float* __restrict__ Wd, const float* __restrict__ bd,
    const float* __restrict__ W2, const float* __restrict__ b2,
    const float* __restrict__ W3, const float* __restrict__ b3,
    float* __restrict__ out, int n_edges, int n_nodes)
{
    extern __shared__ __align__(16) float dsm[];

    int tid = threadIdx.x;
    if (tid == 0) {
        // dtype probe: int32 data read as int64 pairs -> values outside [0,n)
        const long long* p = (const long long*)ei;
        int ok = 1;
        for (int i = 0; i < 64; i++) {
            long long v = p[i];
            if (v < 0 || v >= n_nodes) { ok = 0; break; }
        }
        ((int*)dsm)[FLAG_OFF] = ok;
    }
    // Wdiff (f32, padded to 40 cols) -> smem
    for (int i = tid; i < LDIM * NPAD; i += 128) {
        int k = i / NPAD, j = i - k * NPAD;
        float v = 0.f;
        if (j < HD)        v = W1[(LDIM + k) * HD + j] - W1[k * HD + j];
        else if (j < NCOL) v = Wd[(LDIM + k) * EDIM + (j - HD)] - Wd[k * EDIM + (j - HD)];
        dsm[W_OFF_WD + i] = v;
    }
    for (int i = tid; i < HD * HD; i += 128)   dsm[W_OFF_W2 + i] = W2[i];
    for (int i = tid; i < HD * EDIM; i += 128) dsm[W_OFF_W3 + i] = W3[i];
    if (tid < HD)   dsm[W_OFF_B2 + tid] = b2[tid];
    if (tid < EDIM) dsm[W_OFF_BO + tid] = b3[tid];
    __syncthreads();
    int s_is64 = ((const int*)dsm)[FLAG_OFF];

    int warp = tid >> 5, lane = tid & 31;
    int tile_base = (blockIdx.x * NWARPS + warp) * EPW;
    if (tile_base >= n_edges) return;

    int e  = tile_base + lane;
    int ec = (e < n_edges) ? e : (n_edges - 1);

    unsigned s, t;
    if (s_is64) {
        s = (unsigned)((const long long*)ei)[ec];
        t = (unsigned)((const long long*)ei)[(size_t)n_edges + ec];
    } else {
        s = (unsigned)((const int*)ei)[ec];
        t = (unsigned)((const int*)ei)[(size_t)n_edges + ec];
    }
    unsigned nm1 = (unsigned)(n_nodes - 1);
    s = (s < nm1) ? s : nm1;
    t = (t < nm1) ? t : nm1;

    float* sm_m = dsm + TILE_OFF + warp * PER_WARP;   // [32][M_ST], aliased
    float* sm_c = sm_m;                               // [32][C_ST] after MMA

    const unsigned FULL = 0xffffffffu;
    int half = lane >> 4, li = lane & 15;
    int gid = lane >> 2, tig = lane & 3;              // MMA group / thread-in-group

    // ---- Phase A: gather m = max(x_s, x_t), whole rows, 32 passes ----
    #pragma unroll 4
    for (int ee = 0; ee < EPW; ee++) {
        unsigned sr = __shfl_sync(FULL, s, ee);
        unsigned tr = __shfl_sync(FULL, t, ee);
        unsigned row = half ? tr : sr;
        const float4* px = (const float4*)(x + (size_t)row * LDIM);
        float4 v = __ldg(px + li);
        float4 m;
        m.x = fmaxf(v.x, __shfl_xor_sync(FULL, v.x, 16));
        m.y = fmaxf(v.y, __shfl_xor_sync(FULL, v.y, 16));
        m.z = fmaxf(v.z, __shfl_xor_sync(FULL, v.z, 16));
        m.w = fmaxf(v.w, __shfl_xor_sync(FULL, v.w, 16));
        if (lane < 16) *(float4*)(sm_m + ee * M_ST + li * 4) = m;
    }
    __syncwarp();

    // ---- Phase B: MMA, D[2 mt][5 nt][4] ----
    float d[2][5][4];
    #pragma unroll
    for (int mt = 0; mt < 2; mt++)
        #pragma unroll
        for (int nt = 0; nt < 5; nt++)
            #pragma unroll
            for (int q = 0; q < 4; q++) d[mt][nt][q] = 0.f;

    #pragma unroll 1
    for (int kt = 0; kt < 8; kt++) {
        unsigned ahi[2][4], alo[2][4];
        #pragma unroll
        for (int mt = 0; mt < 2; mt++) {
            int r0 = 16 * mt + gid;
            float a0 = sm_m[(r0)     * M_ST + 8 * kt + tig];
            float a1 = sm_m[(r0 + 8) * M_ST + 8 * kt + tig];
            float a2 = sm_m[(r0)     * M_ST + 8 * kt + tig + 4];
            float a3 = sm_m[(r0 + 8) * M_ST + 8 * kt + tig + 4];
            split_tf32(a0, ahi[mt][0], alo[mt][0]);
            split_tf32(a1, ahi[mt][1], alo[mt][1]);
            split_tf32(a2, ahi[mt][2], alo[mt][2]);
            split_tf32(a3, ahi[mt][3], alo[mt][3]);
        }
        #pragma unroll
        for (int nt = 0; nt < 5; nt++) {
            float b0f = dsm[W_OFF_WD + (8 * kt + tig)     * NPAD + 8 * nt + gid];
            float b1f = dsm[W_OFF_WD + (8 * kt + tig + 4) * NPAD + 8 * nt + gid];
            unsigned bh0, bl0, bh1, bl1;
            split_tf32(b0f, bh0, bl0);
            split_tf32(b1f, bh1, bl1);
            #pragma unroll
            for (int mt = 0; mt < 2; mt++) {
                mma_tf32(d[mt][nt], ahi[mt], bh0, bh1);   // hi*hi
                mma_tf32(d[mt][nt], ahi[mt], bl0, bl1);   // hi*lo
                mma_tf32(d[mt][nt], alo[mt], bh0, bh1);   // lo*hi
            }
        }
    }
    __syncwarp();   // all sm_m reads done before c-tile overwrite

    // ---- Phase C: stage C fragments to c-tile [32][C_ST] ----
    #pragma unroll
    for (int mt = 0; mt < 2; mt++) {
        #pragma unroll
        for (int nt = 0; nt < 5; nt++) {
            int r = 16 * mt + gid;
            int cbase = 8 * nt + 2 * tig;
            *(float2*)(sm_c + (r)     * C_ST + cbase) = make_float2(d[mt][nt][0], d[mt][nt][1]);
            *(float2*)(sm_c + (r + 8) * C_ST + cbase) = make_float2(d[mt][nt][2], d[mt][nt][3]);
        }
    }
    __syncwarp();

    // ---- Phase D: u gather, RMW-add into c-tile ----
    #pragma unroll 4
    for (int ee = 0; ee < EPW; ee++) {
        unsigned sr = __shfl_sync(FULL, s, ee);
        unsigned tr = __shfl_sync(FULL, t, ee);
        unsigned row = half ? tr : sr;
        const float4* pu = (const float4*)(g_u + (size_t)row * NCOL);
        int uli = (li < 9) ? li : 8;
        float4 uv = __ldg(pu + uli);
        float4 us;
        us.x = uv.x + __shfl_xor_sync(FULL, uv.x, 16);
        us.y = uv.y + __shfl_xor_sync(FULL, uv.y, 16);
        us.z = uv.z + __shfl_xor_sync(FULL, uv.z, 16);
        us.w = uv.w + __shfl_xor_sync(FULL, uv.w, 16);
        if (lane < 9) {
            float4* pc = (float4*)(sm_c + ee * C_ST + li * 4);
            float4 cv = *pc;
            cv.x += us.x; cv.y += us.y; cv.z += us.z; cv.w += us.w;
            *pc = cv;
        }
    }
    __syncwarp();

    // ---- Phase E: per-thread tail (b1/bd already folded via u) ----
    const float* crow = sm_c + lane * C_ST;
    float h[HD], cd[EDIM];
    #pragma unroll
    for (int j4 = 0; j4 < 8; j4++) {
        float4 v = *(const float4*)(crow + j4 * 4);
        h[4 * j4 + 0] = fmaxf(v.x, 0.f);
        h[4 * j4 + 1] = fmaxf(v.y, 0.f);
        h[4 * j4 + 2] = fmaxf(v.z, 0.f);
        h[4 * j4 + 3] = fmaxf(v.w, 0.f);
    }
    {
        float4 v = *(const float4*)(crow + 32);
        cd[0] = v.x; cd[1] = v.y; cd[2] = v.z; cd[3] = v.w;
    }

    // GEMM2: h @ W2 (+ b2, + residual h, relu)
    ull acc2[HD / 2];
    #pragma unroll
    for (int i = 0; i < HD / 2; i++) acc2[i] = 0ULL;
    #pragma unroll 8
    for (int k = 0; k < HD; k++) {
        ull hk = pack2(h[k]);
        const ulonglong2* wr = (const ulonglong2*)(dsm + W_OFF_W2 + k * HD);
        #pragma unroll
        for (int j4 = 0; j4 < HD / 4; j4++) {
            ulonglong2 w = wr[j4];
            acc2[2 * j4 + 0] = fma2(hk, w.x, acc2[2 * j4 + 0]);
            acc2[2 * j4 + 1] = fma2(hk, w.y, acc2[2 * j4 + 1]);
        }
    }
    #pragma unroll
    for (int i = 0; i < HD / 2; i++) {
        float lo, hi; unpack2(acc2[i], lo, hi);
        h[2 * i + 0] = fmaxf(lo + dsm[W_OFF_B2 + 2 * i + 0] + h[2 * i + 0], 0.f);
        h[2 * i + 1] = fmaxf(hi + dsm[W_OFF_B2 + 2 * i + 1] + h[2 * i + 1], 0.f);
    }

    // GEMM3: h2 @ W3
    ull o01 = 0ULL, o23 = 0ULL;
    #pragma unroll 8
    for (int k = 0; k < HD; k++) {
        ull hk = pack2(h[k]);
        ulonglong2 w = *(const ulonglong2*)(dsm + W_OFF_W3 + k * EDIM);
        o01 = fma2(hk, w.x, o01);
        o23 = fma2(hk, w.y, o23);
    }

    if (e < n_edges) {
        float a, b;
        float4 r;
        unpack2(o01, a, b);
        r.x = a + cd[0] + dsm[W_OFF_BO + 0];
        r.y = b + cd[1] + dsm[W_OFF_BO + 1];
        unpack2(o23, a, b);
        r.z = a + cd[2] + dsm[W_OFF_BO + 2];
        r.w = b + cd[3] + dsm[W_OFF_BO + 3];
        ((float4*)out)[e] = r;
    }
}

// ---------------------------------------------------------------------------
extern "C" void kernel_launch(void* const* d_in, const int* in_sizes, int n_in,
                              void* d_out, int out_size) {
    const float* x  = (const float*)d_in[0];
    const void*  ei = d_in[1];
    const float* Wd = (const float*)d_in[2];
    const float* bd = (const float*)d_in[3];
    const float* W1 = (const float*)d_in[4];
    const float* b1 = (const float*)d_in[5];
    const float* W2 = (const float*)d_in[6];
    const float* b2 = (const float*)d_in[7];
    const float* W3 = (const float*)d_in[8];
    const float* b3 = (const float*)d_in[9];
    float* out = (float*)d_out;

    int n_nodes = in_sizes[0] / LDIM;
    if (n_nodes > NN_MAX) n_nodes = NN_MAX;
    int n_edges = in_sizes[1] / 2;

    static int attr_done = 0;
    if (!attr_done) {
        cudaFuncSetAttribute(edge_kernel,
                             cudaFuncAttributeMaxDynamicSharedMemorySize,
                             SMEM_BYTES);
        attr_done = 1;
    }

    precompute_u<<<(n_nodes + 255) / 256, 256>>>(x, W1, Wd, b1, bd, n_nodes);

    int edges_per_block = NWARPS * EPW;   // 128
    int blocks = (n_edges + edges_per_block - 1) / edges_per_block;
    edge_kernel<<<blocks, 128, SMEM_BYTES>>>(x, ei, W1, b1, Wd, bd,
                                             W2, b2, W3, b3, out, n_edges, n_nodes);
}

// round 12
// speedup vs baseline: 1.0101x; 1.0101x over previous
#include <cuda_runtime.h>
#include <cuda_bf16.h>
#include <cstdint>

typedef unsigned long long ull;

#define NN_MAX 100000
#define LDIM 64
#define HD 32
#define EDIM 4
#define NCOL 36   // 32 (W1) + 4 (W_direct) fused columns
#define NPAD 40   // NCOL padded to 5 n8-tiles

// dynamic smem layout (float offsets)
#define W_OFF_WDH 0       // Wdiff hi (tf32-rounded f32) [64][40]
#define W_OFF_WDL 2560    // Wdiff lo (bf16) [64][40] = 1280 float slots
#define W_OFF_W2  3840    // [32][32]
#define W_OFF_W3  4864    // [32][4]
#define W_OFF_B2  4992
#define W_OFF_BO  5024    // b3 only (bd folded into g_u)
#define FLAG_OFF  5028
#define TILE_OFF  5032    // *4 = 20128 B, 16B aligned
#define M_ST      68      // m-tile stride (17 f4, odd -> conflict-free)
#define C_ST      44      // c-tile stride (11 f4, odd -> conflict-free)
#define EPW       32      // edges per warp
#define PER_WARP  2176    // max(32*68, 32*44) floats, aliased
#define NWARPS    4
#define SMEM_FLOATS (TILE_OFF + NWARPS * PER_WARP)   // 13736
#define SMEM_BYTES  (SMEM_FLOATS * 4)                // 54944 -> 4 blocks/SM

// Scratch: u[node][j] = sum_k x[node][k]*[W1|Wd][k][j] + 0.5*(b1|bd)[j]
__device__ __align__(16) float g_u[NN_MAX * NCOL];

__device__ __forceinline__ ull pack2(float a) {
    ull r; asm("mov.b64 %0, {%1, %1};" : "=l"(r) : "f"(a)); return r;
}
__device__ __forceinline__ ull fma2(ull a, ull b, ull c) {
    ull d; asm("fma.rn.f32x2 %0, %1, %2, %3;" : "=l"(d) : "l"(a), "l"(b), "l"(c)); return d;
}
__device__ __forceinline__ void unpack2(ull v, float& lo, float& hi) {
    asm("mov.b64 {%0, %1}, %2;" : "=f"(lo), "=f"(hi) : "l"(v));
}
__device__ __forceinline__ unsigned tf32_of(float v) {
    unsigned r; asm("cvt.rna.tf32.f32 %0, %1;" : "=r"(r) : "f"(v)); return r;
}
__device__ __forceinline__ void split_tf32(float v, unsigned& hi, unsigned& lo) {
    hi = tf32_of(v);
    lo = tf32_of(v - __uint_as_float(hi));
}
__device__ __forceinline__ void mma_tf32(float* d, const unsigned* a,
                                         unsigned b0, unsigned b1) {
    asm("mma.sync.aligned.m16n8k8.row.col.f32.tf32.tf32.f32 "
        "{%0,%1,%2,%3}, {%4,%5,%6,%7}, {%8,%9}, {%0,%1,%2,%3};"
        : "+f"(d[0]), "+f"(d[1]), "+f"(d[2]), "+f"(d[3])
        : "r"(a[0]), "r"(a[1]), "r"(a[2]), "r"(a[3]), "r"(b0), "r"(b1));
}

// ---------------------------------------------------------------------------
// Kernel 1: per-node u = x @ [W1[:64] | Wd[:64]] + 0.5*[b1 | bd]
// ---------------------------------------------------------------------------
__global__ void __launch_bounds__(256) precompute_u(
    const float* __restrict__ x,
    const float* __restrict__ W1,
    const float* __restrict__ Wd,
    const float* __restrict__ b1,
    const float* __restrict__ bd,
    int n_nodes)
{
    __shared__ __align__(16) float sW[LDIM][NCOL];
    __shared__ float sb[NCOL];
    int tid = threadIdx.x;
    for (int i = tid; i < LDIM * NCOL; i += 256) {
        int k = i / NCOL, j = i - k * NCOL;
        sW[k][j] = (j < HD) ? W1[k * HD + j] : Wd[k * EDIM + (j - HD)];
    }
    if (tid < NCOL) sb[tid] = 0.5f * ((tid < HD) ? b1[tid] : bd[tid - HD]);
    __syncthreads();

    int node = blockIdx.x * 256 + tid;
    if (node >= n_nodes) return;

    float acc[NCOL];
    #pragma unroll
    for (int j = 0; j < NCOL; j++) acc[j] = sb[j];

    const float4* xr = (const float4*)(x + (size_t)node * LDIM);
    #pragma unroll 4
    for (int k4 = 0; k4 < LDIM / 4; k4++) {
        float4 v = __ldg(xr + k4);
        #pragma unroll
        for (int j = 0; j < NCOL; j++) {
            acc[j] = fmaf(v.x, sW[4 * k4 + 0][j], acc[j]);
            acc[j] = fmaf(v.y, sW[4 * k4 + 1][j], acc[j]);
            acc[j] = fmaf(v.z, sW[4 * k4 + 2][j], acc[j]);
            acc[j] = fmaf(v.w, sW[4 * k4 + 3][j], acc[j]);
        }
    }
    float4* ur = (float4*)(g_u + (size_t)node * NCOL);
    #pragma unroll
    for (int j4 = 0; j4 < NCOL / 4; j4++) {
        float4 r;
        r.x = acc[4 * j4 + 0]; r.y = acc[4 * j4 + 1];
        r.z = acc[4 * j4 + 2]; r.w = acc[4 * j4 + 3];
        ur[j4] = r;
    }
}

// ---------------------------------------------------------------------------
// Kernel 2: GEMM1 on tensor cores (tf32 3-term split, PRE-SPLIT weights),
// scalar f32x2 tail. B operands need zero cvt at load: hi is tf32-rounded
// f32 (bit pattern passed straight to mma), lo is bf16<<16.
// ---------------------------------------------------------------------------
__global__ void __launch_bounds__(128, 4) edge_kernel(
    const float* __restrict__ x,
    const void* __restrict__ ei,
    const float* __restrict__ W1, const float* __restrict__ b1,
    const float* __restrict__ Wd, const float* __restrict__ bd,
    const float* __restrict__ W2, const float* __restrict__ b2,
    const float* __restrict__ W3, const float* __restrict__ b3,
    float* __restrict__ out, int n_edges, int n_nodes)
{
    extern __shared__ __align__(16) float dsm[];

    int tid = threadIdx.x;
    if (tid == 0) {
        // dtype probe: int32 data read as int64 pairs -> values outside [0,n)
        const long long* p = (const long long*)ei;
        int ok = 1;
        for (int i = 0; i < 64; i++) {
            long long v = p[i];
            if (v < 0 || v >= n_nodes) { ok = 0; break; }
        }
        ((int*)dsm)[FLAG_OFF] = ok;
    }
    // Wdiff: pre-split into tf32-hi (f32 slot) + bf16-lo
    unsigned short* wdl = (unsigned short*)(dsm + W_OFF_WDL);
    for (int i = tid; i < LDIM * NPAD; i += 128) {
        int k = i / NPAD, j = i - k * NPAD;
        float v = 0.f;
        if (j < HD)        v = W1[(LDIM + k) * HD + j] - W1[k * HD + j];
        else if (j < NCOL) v = Wd[(LDIM + k) * EDIM + (j - HD)] - Wd[k * EDIM + (j - HD)];
        unsigned hi = tf32_of(v);
        float lo = v - __uint_as_float(hi);
        dsm[W_OFF_WDH + i] = __uint_as_float(hi);
        __nv_bfloat16 lb = __float2bfloat16(lo);
        wdl[i] = *reinterpret_cast<unsigned short*>(&lb);
    }
    for (int i = tid; i < HD * HD; i += 128)   dsm[W_OFF_W2 + i] = W2[i];
    for (int i = tid; i < HD * EDIM; i += 128) dsm[W_OFF_W3 + i] = W3[i];
    if (tid < HD)   dsm[W_OFF_B2 + tid] = b2[tid];
    if (tid < EDIM) dsm[W_OFF_BO + tid] = b3[tid];
    __syncthreads();
    int s_is64 = ((const int*)dsm)[FLAG_OFF];

    int warp = tid >> 5, lane = tid & 31;
    int tile_base = (blockIdx.x * NWARPS + warp) * EPW;
    if (tile_base >= n_edges) return;

    int e  = tile_base + lane;
    int ec = (e < n_edges) ? e : (n_edges - 1);

    unsigned s, t;
    if (s_is64) {
        s = (unsigned)((const long long*)ei)[ec];
        t = (unsigned)((const long long*)ei)[(size_t)n_edges + ec];
    } else {
        s = (unsigned)((const int*)ei)[ec];
        t = (unsigned)((const int*)ei)[(size_t)n_edges + ec];
    }
    unsigned nm1 = (unsigned)(n_nodes - 1);
    s = (s < nm1) ? s : nm1;
    t = (t < nm1) ? t : nm1;

    float* sm_m = dsm + TILE_OFF + warp * PER_WARP;   // [32][M_ST], aliased
    float* sm_c = sm_m;                               // [32][C_ST] after MMA

    const unsigned FULL = 0xffffffffu;
    int half = lane >> 4, li = lane & 15;
    int gid = lane >> 2, tig = lane & 3;              // MMA group / thread-in-group

    // ---- Phase A: gather m = max(x_s, x_t), whole rows, 32 passes ----
    #pragma unroll 4
    for (int ee = 0; ee < EPW; ee++) {
        unsigned sr = __shfl_sync(FULL, s, ee);
        unsigned tr = __shfl_sync(FULL, t, ee);
        unsigned row = half ? tr : sr;
        const float4* px = (const float4*)(x + (size_t)row * LDIM);
        float4 v = __ldg(px + li);
        float4 m;
        m.x = fmaxf(v.x, __shfl_xor_sync(FULL, v.x, 16));
        m.y = fmaxf(v.y, __shfl_xor_sync(FULL, v.y, 16));
        m.z = fmaxf(v.z, __shfl_xor_sync(FULL, v.z, 16));
        m.w = fmaxf(v.w, __shfl_xor_sync(FULL, v.w, 16));
        if (lane < 16) *(float4*)(sm_m + ee * M_ST + li * 4) = m;
    }
    __syncwarp();

    // ---- Phase B: MMA, D[2 mt][5 nt][4] ----
    float d[2][5][4];
    #pragma unroll
    for (int mt = 0; mt < 2; mt++)
        #pragma unroll
        for (int nt = 0; nt < 5; nt++)
            #pragma unroll
            for (int q = 0; q < 4; q++) d[mt][nt][q] = 0.f;

    const unsigned short* wl = (const unsigned short*)(dsm + W_OFF_WDL);

    #pragma unroll 2
    for (int kt = 0; kt < 8; kt++) {
        unsigned ahi[2][4], alo[2][4];
        #pragma unroll
        for (int mt = 0; mt < 2; mt++) {
            int r0 = 16 * mt + gid;
            float a0 = sm_m[(r0)     * M_ST + 8 * kt + tig];
            float a1 = sm_m[(r0 + 8) * M_ST + 8 * kt + tig];
            float a2 = sm_m[(r0)     * M_ST + 8 * kt + tig + 4];
            float a3 = sm_m[(r0 + 8) * M_ST + 8 * kt + tig + 4];
            split_tf32(a0, ahi[mt][0], alo[mt][0]);
            split_tf32(a1, ahi[mt][1], alo[mt][1]);
            split_tf32(a2, ahi[mt][2], alo[mt][2]);
            split_tf32(a3, ahi[mt][3], alo[mt][3]);
        }
        #pragma unroll
        for (int nt = 0; nt < 5; nt++) {
            int i0 = (8 * kt + tig)     * NPAD + 8 * nt + gid;
            int i1 = (8 * kt + tig + 4) * NPAD + 8 * nt + gid;
            unsigned bh0 = __float_as_uint(dsm[W_OFF_WDH + i0]);
            unsigned bh1 = __float_as_uint(dsm[W_OFF_WDH + i1]);
            unsigned bl0 = ((unsigned)wl[i0]) << 16;
            unsigned bl1 = ((unsigned)wl[i1]) << 16;
            #pragma unroll
            for (int mt = 0; mt < 2; mt++) {
                mma_tf32(d[mt][nt], ahi[mt], bh0, bh1);   // hi*hi
                mma_tf32(d[mt][nt], ahi[mt], bl0, bl1);   // hi*lo
                mma_tf32(d[mt][nt], alo[mt], bh0, bh1);   // lo*hi
            }
        }
    }
    __syncwarp();   // all sm_m reads done before c-tile overwrite

    // ---- Phase C: stage C fragments to c-tile [32][C_ST] ----
    #pragma unroll
    for (int mt = 0; mt < 2; mt++) {
        #pragma unroll
        for (int nt = 0; nt < 5; nt++) {
            int r = 16 * mt + gid;
            int cbase = 8 * nt + 2 * tig;
            *(float2*)(sm_c + (r)     * C_ST + cbase) = make_float2(d[mt][nt][0], d[mt][nt][1]);
            *(float2*)(sm_c + (r + 8) * C_ST + cbase) = make_float2(d[mt][nt][2], d[mt][nt][3]);
        }
    }
    __syncwarp();

    // ---- Phase D: u gather, RMW-add into c-tile ----
    #pragma unroll 4
    for (int ee = 0; ee < EPW; ee++) {
        unsigned sr = __shfl_sync(FULL, s, ee);
        unsigned tr = __shfl_sync(FULL, t, ee);
        unsigned row = half ? tr : sr;
        const float4* pu = (const float4*)(g_u + (size_t)row * NCOL);
        int uli = (li < 9) ? li : 8;
        float4 uv = __ldg(pu + uli);
        float4 us;
        us.x = uv.x + __shfl_xor_sync(FULL, uv.x, 16);
        us.y = uv.y + __shfl_xor_sync(FULL, uv.y, 16);
        us.z = uv.z + __shfl_xor_sync(FULL, uv.z, 16);
        us.w = uv.w + __shfl_xor_sync(FULL, uv.w, 16);
        if (lane < 9) {
            float4* pc = (float4*)(sm_c + ee * C_ST + li * 4);
            float4 cv = *pc;
            cv.x += us.x; cv.y += us.y; cv.z += us.z; cv.w += us.w;
            *pc = cv;
        }
    }
    __syncwarp();

    // ---- Phase E: per-thread tail (b1/bd already folded via u) ----
    const float* crow = sm_c + lane * C_ST;
    float h[HD], cd[EDIM];
    #pragma unroll
    for (int j4 = 0; j4 < 8; j4++) {
        float4 v = *(const float4*)(crow + j4 * 4);
        h[4 * j4 + 0] = fmaxf(v.x, 0.f);
        h[4 * j4 + 1] = fmaxf(v.y, 0.f);
        h[4 * j4 + 2] = fmaxf(v.z, 0.f);
        h[4 * j4 + 3] = fmaxf(v.w, 0.f);
    }
    {
        float4 v = *(const float4*)(crow + 32);
        cd[0] = v.x; cd[1] = v.y; cd[2] = v.z; cd[3] = v.w;
    }

    // GEMM2: h @ W2 (+ b2, + residual h, relu)
    ull acc2[HD / 2];
    #pragma unroll
    for (int i = 0; i < HD / 2; i++) acc2[i] = 0ULL;
    #pragma unroll 8
    for (int k = 0; k < HD; k++) {
        ull hk = pack2(h[k]);
        const ulonglong2* wr = (const ulonglong2*)(dsm + W_OFF_W2 + k * HD);
        #pragma unroll
        for (int j4 = 0; j4 < HD / 4; j4++) {
            ulonglong2 w = wr[j4];
            acc2[2 * j4 + 0] = fma2(hk, w.x, acc2[2 * j4 + 0]);
            acc2[2 * j4 + 1] = fma2(hk, w.y, acc2[2 * j4 + 1]);
        }
    }
    #pragma unroll
    for (int i = 0; i < HD / 2; i++) {
        float lo, hi; unpack2(acc2[i], lo, hi);
        h[2 * i + 0] = fmaxf(lo + dsm[W_OFF_B2 + 2 * i + 0] + h[2 * i + 0], 0.f);
        h[2 * i + 1] = fmaxf(hi + dsm[W_OFF_B2 + 2 * i + 1] + h[2 * i + 1], 0.f);
    }

    // GEMM3: h2 @ W3
    ull o01 = 0ULL, o23 = 0ULL;
    #pragma unroll 8
    for (int k = 0; k < HD; k++) {
        ull hk = pack2(h[k]);
        ulonglong2 w = *(const ulonglong2*)(dsm + W_OFF_W3 + k * EDIM);
        o01 = fma2(hk, w.x, o01);
        o23 = fma2(hk, w.y, o23);
    }

    if (e < n_edges) {
        float a, b;
        float4 r;
        unpack2(o01, a, b);
        r.x = a + cd[0] + dsm[W_OFF_BO + 0];
        r.y = b + cd[1] + dsm[W_OFF_BO + 1];
        unpack2(o23, a, b);
        r.z = a + cd[2] + dsm[W_OFF_BO + 2];
        r.w = b + cd[3] + dsm[W_OFF_BO + 3];
        ((float4*)out)[e] = r;
    }
}

// ---------------------------------------------------------------------------
extern "C" void kernel_launch(void* const* d_in, const int* in_sizes, int n_in,
                              void* d_out, int out_size) {
    const float* x  = (const float*)d_in[0];
    const void*  ei = d_in[1];
    const float* Wd = (const float*)d_in[2];
    const float* bd = (const float*)d_in[3];
    const float* W1 = (const float*)d_in[4];
    const float* b1 = (const float*)d_in[5];
    const float* W2 = (const float*)d_in[6];
    const float* b2 = (const float*)d_in[7];
    const float* W3 = (const float*)d_in[8];
    const float* b3 = (const float*)d_in[9];
    float* out = (float*)d_out;

    int n_nodes = in_sizes[0] / LDIM;
    if (n_nodes > NN_MAX) n_nodes = NN_MAX;
    int n_edges = in_sizes[1] / 2;

    static int attr_done = 0;
    if (!attr_done) {
        cudaFuncSetAttribute(edge_kernel,
                             cudaFuncAttributeMaxDynamicSharedMemorySize,
                             SMEM_BYTES);
        attr_done = 1;
    }

    precompute_u<<<(n_nodes + 255) / 256, 256>>>(x, W1, Wd, b1, bd, n_nodes);

    int edges_per_block = NWARPS * EPW;   // 128
    int blocks = (n_edges + edges_per_block - 1) / edges_per_block;
    edge_kernel<<<blocks, 128, SMEM_BYTES>>>(x, ei, W1, b1, Wd, bd,
                                             W2, b2, W3, b3, out, n_edges, n_nodes);
}

// round 14
// speedup vs baseline: 1.2851x; 1.2722x over previous
#include <cuda_runtime.h>
#include <cstdint>

typedef unsigned long long ull;

#define NN_MAX 100000
#define LDIM 64
#define HD 32
#define EDIM 4
#define NCOL 36   // 32 (W1) + 4 (W_direct) fused columns

// ---- constant-memory weight block (published via async memcpy from g_stage)
struct WConst {
    float wd[LDIM * NCOL];   // Wdiff = W[64:] - W[:64], fused [W1|Wd]
    float w2[HD * HD];
    float w3[HD * EDIM];
    float b1[HD];
    float b2[HD];
    float bo[EDIM];          // b3 + bd
};
__constant__ __align__(16) WConst c_w;
__device__   __align__(16) WConst g_stage;

// smem: flag + per-warp tiles only (weights live in constant space)
#define FLAG_OFF  0
#define TILE_OFF  4                         // 16 B aligned
#define M_CH      20                        // chunk row stride (5 f4, odd -> conflict-free)
#define EPW       64                        // edges per warp (EPT=2)
#define PER_WARP  2304                      // m-chunk (64*20) / u (64*36) aliased
#define NWARPS    4
#define SMEM_FLOATS (TILE_OFF + NWARPS * PER_WARP)  // 9220
#define SMEM_BYTES  (SMEM_FLOATS * 4)               // 36880

// Scratch: u[node][j] = sum_{k<64} x[node][k] * [W1 | Wd][k][j]
__device__ __align__(16) float g_u[NN_MAX * NCOL];

__device__ __forceinline__ ull pack2(float a) {
    ull r; asm("mov.b64 %0, {%1, %1};" : "=l"(r) : "f"(a)); return r;
}
__device__ __forceinline__ ull fma2(ull a, ull b, ull c) {
    ull d; asm("fma.rn.f32x2 %0, %1, %2, %3;" : "=l"(d) : "l"(a), "l"(b), "l"(c)); return d;
}
__device__ __forceinline__ ull add2(ull a, ull b) {
    ull d; asm("add.rn.f32x2 %0, %1, %2;" : "=l"(d) : "l"(a), "l"(b)); return d;
}
__device__ __forceinline__ void unpack2(ull v, float& lo, float& hi) {
    asm("mov.b64 {%0, %1}, %2;" : "=f"(lo), "=f"(hi) : "l"(v));
}

// ---------------------------------------------------------------------------
// Kernel 0: derive Wdiff / combined biases into the staging struct.
// ---------------------------------------------------------------------------
__global__ void __launch_bounds__(256) prep_weights(
    const float* __restrict__ W1, const float* __restrict__ b1,
    const float* __restrict__ Wd, const float* __restrict__ bd,
    const float* __restrict__ W2, const float* __restrict__ b2,
    const float* __restrict__ W3, const float* __restrict__ b3)
{
    int tid = threadIdx.x;
    for (int i = tid; i < LDIM * NCOL; i += 256) {
        int k = i / NCOL, j = i - k * NCOL;
        float hi, lo;
        if (j < HD) { hi = W1[(LDIM + k) * HD + j];        lo = W1[k * HD + j]; }
        else        { hi = Wd[(LDIM + k) * EDIM + (j-HD)]; lo = Wd[k * EDIM + (j-HD)]; }
        g_stage.wd[i] = hi - lo;
    }
    for (int i = tid; i < HD * HD; i += 256)   g_stage.w2[i] = W2[i];
    for (int i = tid; i < HD * EDIM; i += 256) g_stage.w3[i] = W3[i];
    if (tid < HD)  { g_stage.b1[tid] = b1[tid]; g_stage.b2[tid] = b2[tid]; }
    if (tid < EDIM) g_stage.bo[tid] = b3[tid] + bd[tid];
}

// ---------------------------------------------------------------------------
// Kernel 1: per-node precompute u = x[:, :] @ [W1[:64] | Wd[:64]]
// ---------------------------------------------------------------------------
__global__ void __launch_bounds__(256) precompute_u(
    const float* __restrict__ x,
    const float* __restrict__ W1,
    const float* __restrict__ Wd,
    int n_nodes)
{
    __shared__ __align__(16) float sW[LDIM][NCOL];
    int tid = threadIdx.x;
    for (int i = tid; i < LDIM * NCOL; i += 256) {
        int k = i / NCOL, j = i - k * NCOL;
        sW[k][j] = (j < HD) ? W1[k * HD + j] : Wd[k * EDIM + (j - HD)];
    }
    __syncthreads();

    int node = blockIdx.x * 256 + tid;
    if (node >= n_nodes) return;

    float acc[NCOL];
    #pragma unroll
    for (int j = 0; j < NCOL; j++) acc[j] = 0.f;

    const float4* xr = (const float4*)(x + (size_t)node * LDIM);
    #pragma unroll 4
    for (int k4 = 0; k4 < LDIM / 4; k4++) {
        float4 v = __ldg(xr + k4);
        #pragma unroll
        for (int j = 0; j < NCOL; j++) {
            acc[j] = fmaf(v.x, sW[4 * k4 + 0][j], acc[j]);
            acc[j] = fmaf(v.y, sW[4 * k4 + 1][j], acc[j]);
            acc[j] = fmaf(v.z, sW[4 * k4 + 2][j], acc[j]);
            acc[j] = fmaf(v.w, sW[4 * k4 + 3][j], acc[j]);
        }
    }
    float4* ur = (float4*)(g_u + (size_t)node * NCOL);
    #pragma unroll
    for (int j4 = 0; j4 < NCOL / 4; j4++) {
        float4 r;
        r.x = acc[4 * j4 + 0]; r.y = acc[4 * j4 + 1];
        r.z = acc[4 * j4 + 2]; r.w = acc[4 * j4 + 3];
        ur[j4] = r;
    }
}

// ---------------------------------------------------------------------------
// Sequential tail: bias+relu -> GEMM2 (residual) -> GEMM3 -> store, one edge.
// All weights from constant space (uniform addresses -> LDCU path).
// ---------------------------------------------------------------------------
__device__ __forceinline__ void tail_edge(
    const ull (&acc)[NCOL / 2],
    float* __restrict__ out, int e, int n_edges)
{
    if (e >= n_edges) return;

    float h[HD], cd[EDIM];
    #pragma unroll
    for (int i = 0; i < HD / 2; i++) {
        float lo, hi; unpack2(acc[i], lo, hi);
        h[2 * i + 0] = fmaxf(lo + c_w.b1[2 * i + 0], 0.f);
        h[2 * i + 1] = fmaxf(hi + c_w.b1[2 * i + 1], 0.f);
    }
    unpack2(acc[16], cd[0], cd[1]);
    unpack2(acc[17], cd[2], cd[3]);

    // GEMM2: h @ W2
    ull acc2[HD / 2];
    #pragma unroll
    for (int i = 0; i < HD / 2; i++) acc2[i] = 0ULL;
    #pragma unroll 8
    for (int k = 0; k < HD; k++) {
        ull hk = pack2(h[k]);
        const ulonglong2* wr = (const ulonglong2*)(c_w.w2 + k * HD);
        #pragma unroll
        for (int j4 = 0; j4 < HD / 4; j4++) {
            ulonglong2 w = wr[j4];
            acc2[2 * j4 + 0] = fma2(hk, w.x, acc2[2 * j4 + 0]);
            acc2[2 * j4 + 1] = fma2(hk, w.y, acc2[2 * j4 + 1]);
        }
    }
    // residual + relu, h <- h2
    #pragma unroll
    for (int i = 0; i < HD / 2; i++) {
        float lo, hi; unpack2(acc2[i], lo, hi);
        h[2 * i + 0] = fmaxf(lo + c_w.b2[2 * i + 0] + h[2 * i + 0], 0.f);
        h[2 * i + 1] = fmaxf(hi + c_w.b2[2 * i + 1] + h[2 * i + 1], 0.f);
    }

    // GEMM3: h2 @ W3
    ull o01 = 0ULL, o23 = 0ULL;
    #pragma unroll 8
    for (int k = 0; k < HD; k++) {
        ull hk = pack2(h[k]);
        ulonglong2 w = *(const ulonglong2*)(c_w.w3 + k * EDIM);
        o01 = fma2(hk, w.x, o01);
        o23 = fma2(hk, w.y, o23);
    }
    float a, b;
    float4 r;
    unpack2(o01, a, b);
    r.x = a + cd[0] + c_w.bo[0];
    r.y = b + cd[1] + c_w.bo[1];
    unpack2(o23, a, b);
    r.z = a + cd[2] + c_w.bo[2];
    r.w = b + cd[3] + c_w.bo[3];
    ((float4*)out)[e] = r;
}

// ---------------------------------------------------------------------------
// Kernel 2: warp-cooperative edge MLP, 2 edges/thread, k-chunked m-tile,
// m/u tiles aliased, sequential tail. Weights in __constant__ -> the
// broadcast weight-read class leaves L1tex entirely (uniform-port LDCU).
// ---------------------------------------------------------------------------
__global__ void __launch_bounds__(128, 4) edge_kernel(
    const float* __restrict__ x,
    const void* __restrict__ ei,
    float* __restrict__ out, int n_edges, int n_nodes)
{
    extern __shared__ __align__(16) float dsm[];

    int tid = threadIdx.x;
    if (tid == 0) {
        // dtype probe: int32 data read as int64 pairs -> values outside [0,n)
        const long long* p = (const long long*)ei;
        int ok = 1;
        for (int i = 0; i < 64; i++) {
            long long v = p[i];
            if (v < 0 || v >= n_nodes) { ok = 0; break; }
        }
        ((int*)dsm)[FLAG_OFF] = ok;
    }
    __syncthreads();
    int s_is64 = ((const int*)dsm)[FLAG_OFF];

    int warp = tid >> 5, lane = tid & 31;
    int tile_base = (blockIdx.x * NWARPS + warp) * EPW;
    if (tile_base >= n_edges) return;

    int e0 = tile_base + lane;
    int e1 = e0 + 32;
    int ec0 = (e0 < n_edges) ? e0 : (n_edges - 1);
    int ec1 = (e1 < n_edges) ? e1 : (n_edges - 1);

    // ---- index loads: dtype-flexible, clamped (never IMA) ----
    unsigned s0, t0, s1, t1;
    if (s_is64) {
        s0 = (unsigned)((const long long*)ei)[ec0];
        t0 = (unsigned)((const long long*)ei)[(size_t)n_edges + ec0];
        s1 = (unsigned)((const long long*)ei)[ec1];
        t1 = (unsigned)((const long long*)ei)[(size_t)n_edges + ec1];
    } else {
        s0 = (unsigned)((const int*)ei)[ec0];
        t0 = (unsigned)((const int*)ei)[(size_t)n_edges + ec0];
        s1 = (unsigned)((const int*)ei)[ec1];
        t1 = (unsigned)((const int*)ei)[(size_t)n_edges + ec1];
    }
    unsigned nm1 = (unsigned)(n_nodes - 1);
    s0 = (s0 < nm1) ? s0 : nm1;  t0 = (t0 < nm1) ? t0 : nm1;
    s1 = (s1 < nm1) ? s1 : nm1;  t1 = (t1 < nm1) ? t1 : nm1;

    float* sm_m = dsm + TILE_OFF + warp * PER_WARP;   // [64][M_CH] chunk tile
    float* sm_u = sm_m;                               // [64][NCOL], aliased

    const unsigned FULL = 0xffffffffu;
    int half  = lane >> 4;        // 0 = s-row, 1 = t-row
    int li    = lane & 15;
    int esub4 = li >> 2;          // edge-within-pass (0..3)
    int f     = lane & 3;         // float4-within-chunk (0..3)

    // ================= GEMM1 in 4 k-chunks of 16 =================
    ull acc0[NCOL / 2], acc1[NCOL / 2];
    #pragma unroll
    for (int i = 0; i < NCOL / 2; i++) { acc0[i] = 0ULL; acc1[i] = 0ULL; }

    #pragma unroll 1
    for (int c = 0; c < 4; c++) {
        __syncwarp();
        // gather chunk c: 16 passes x 4 edges; lanes 0-15 s-rows, 16-31 t-rows
        #pragma unroll 4
        for (int pass = 0; pass < 16; pass++) {
            int ee = pass * 4 + esub4;
            unsigned ssel = (pass < 8) ? s0 : s1;
            unsigned tsel = (pass < 8) ? t0 : t1;
            unsigned sr = __shfl_sync(FULL, ssel, ee & 31);
            unsigned tr = __shfl_sync(FULL, tsel, ee & 31);
            unsigned row = half ? tr : sr;
            const float4* px = (const float4*)(x + (size_t)row * LDIM + c * 16);
            float4 v = __ldg(px + f);
            float4 m;
            m.x = fmaxf(v.x, __shfl_xor_sync(FULL, v.x, 16));
            m.y = fmaxf(v.y, __shfl_xor_sync(FULL, v.y, 16));
            m.z = fmaxf(v.z, __shfl_xor_sync(FULL, v.z, 16));
            m.w = fmaxf(v.w, __shfl_xor_sync(FULL, v.w, 16));
            if (lane < 16) *(float4*)(sm_m + ee * M_CH + f * 4) = m;
        }
        __syncwarp();
        // partial GEMM over this chunk's 16 k-values, both edges
        #pragma unroll
        for (int k4 = 0; k4 < 4; k4++) {
            float4 mv0 = *(const float4*)(sm_m + lane * M_CH + k4 * 4);
            float4 mv1 = *(const float4*)(sm_m + (lane + 32) * M_CH + k4 * 4);
            float a4[4] = {mv0.x, mv0.y, mv0.z, mv0.w};
            float b4[4] = {mv1.x, mv1.y, mv1.z, mv1.w};
            #pragma unroll
            for (int kk = 0; kk < 4; kk++) {
                ull ma = pack2(a4[kk]);
                ull mb = pack2(b4[kk]);
                const ulonglong2* wr = (const ulonglong2*)
                    (c_w.wd + (c * 16 + k4 * 4 + kk) * NCOL);
                #pragma unroll
                for (int j4 = 0; j4 < NCOL / 4; j4++) {
                    ulonglong2 w = wr[j4];
                    acc0[2 * j4 + 0] = fma2(ma, w.x, acc0[2 * j4 + 0]);
                    acc0[2 * j4 + 1] = fma2(ma, w.y, acc0[2 * j4 + 1]);
                    acc1[2 * j4 + 0] = fma2(mb, w.x, acc1[2 * j4 + 0]);
                    acc1[2 * j4 + 1] = fma2(mb, w.y, acc1[2 * j4 + 1]);
                }
            }
        }
    }

    // ---- u gather into the (now dead) m-tile buffer ----
    __syncwarp();
    #pragma unroll 4
    for (int ee = 0; ee < EPW; ee++) {
        unsigned ssel = (ee < 32) ? s0 : s1;
        unsigned tsel = (ee < 32) ? t0 : t1;
        unsigned sr = __shfl_sync(FULL, ssel, ee & 31);
        unsigned tr = __shfl_sync(FULL, tsel, ee & 31);
        unsigned row = half ? tr : sr;
        const float4* pu = (const float4*)(g_u + (size_t)row * NCOL);
        int uli = (li < 9) ? li : 8;
        float4 uv = __ldg(pu + uli);
        float4 us;
        us.x = uv.x + __shfl_xor_sync(FULL, uv.x, 16);
        us.y = uv.y + __shfl_xor_sync(FULL, uv.y, 16);
        us.z = uv.z + __shfl_xor_sync(FULL, uv.z, 16);
        us.w = uv.w + __shfl_xor_sync(FULL, uv.w, 16);
        if (lane < 9) *(float4*)(sm_u + ee * NCOL + li * 4) = us;
    }
    __syncwarp();

    // add presummed u_s + u_t
    const ulonglong2* uu0 = (const ulonglong2*)(sm_u + lane * NCOL);
    const ulonglong2* uu1 = (const ulonglong2*)(sm_u + (lane + 32) * NCOL);
    #pragma unroll
    for (int j4 = 0; j4 < NCOL / 4; j4++) {
        ulonglong2 w0 = uu0[j4];
        ulonglong2 w1 = uu1[j4];
        acc0[2 * j4 + 0] = add2(acc0[2 * j4 + 0], w0.x);
        acc0[2 * j4 + 1] = add2(acc0[2 * j4 + 1], w0.y);
        acc1[2 * j4 + 0] = add2(acc1[2 * j4 + 0], w1.x);
        acc1[2 * j4 + 1] = add2(acc1[2 * j4 + 1], w1.y);
    }

    // ---- sequential per-edge tails ----
    tail_edge(acc0, out, e0, n_edges);
    tail_edge(acc1, out, e1, n_edges);
}

// ---------------------------------------------------------------------------
extern "C" void kernel_launch(void* const* d_in, const int* in_sizes, int n_in,
                              void* d_out, int out_size) {
    const float* x  = (const float*)d_in[0];
    const void*  ei = d_in[1];
    const float* Wd = (const float*)d_in[2];
    const float* bd = (const float*)d_in[3];
    const float* W1 = (const float*)d_in[4];
    const float* b1 = (const float*)d_in[5];
    const float* W2 = (const float*)d_in[6];
    const float* b2 = (const float*)d_in[7];
    const float* W3 = (const float*)d_in[8];
    const float* b3 = (const float*)d_in[9];
    float* out = (float*)d_out;

    int n_nodes = in_sizes[0] / LDIM;
    if (n_nodes > NN_MAX) n_nodes = NN_MAX;
    int n_edges = in_sizes[1] / 2;

    static int attr_done = 0;
    static void* stage_ptr = nullptr;
    if (!attr_done) {
        cudaFuncSetAttribute(edge_kernel,
                             cudaFuncAttributeMaxDynamicSharedMemorySize,
                             SMEM_BYTES);
        cudaGetSymbolAddress(&stage_ptr, g_stage);
        attr_done = 1;
    }

    // 0) derive weights into staging, publish to constant space (D2D memcpy
    //    node — graph-capturable, no allocation)
    prep_weights<<<1, 256>>>(W1, b1, Wd, bd, W2, b2, W3, b3);
    cudaMemcpyToSymbolAsync(c_w, stage_ptr, sizeof(WConst), 0,
                            cudaMemcpyDeviceToDevice, 0);

    // 1) per-node precompute
    precompute_u<<<(n_nodes + 255) / 256, 256>>>(x, W1, Wd, n_nodes);

    // 2) per-edge MLP
    int edges_per_block = NWARPS * EPW;   // 256
    int blocks = (n_edges + edges_per_block - 1) / edges_per_block;
    edge_kernel<<<blocks, 128, SMEM_BYTES>>>(x, ei, out, n_edges, n_nodes);
}